// round 2
// baseline (speedup 1.0000x reference)
#include <cuda_runtime.h>
#include <cstdint>
#include <cstddef>

// Problem constants
#define BB   64
#define TT   1024
#define DD   512
#define HH   1024
#define NG   4096
#define NCTA 128

// ---------------- device scratch (allocation-free, __device__ globals) --------
__device__ float g_xproj[268435456];   // 1 GiB: [t][cta(128)][b(64)][l(32)]
__device__ float g_WhP[4194304];       // 16 MB: f2[((cta*4+gate)*128+ks)*32+lane]
__device__ float g_WxP[2097152];       //  8 MB: f2[(nt*64+ks)*32+lane]
__device__ float g_h[131072];          // [2][b(64)][k(1024)]
__device__ unsigned g_count;
__device__ unsigned g_gen;

// ---------------- helpers -----------------------------------------------------
__device__ __forceinline__ unsigned f2tf32(float x) {
    unsigned u; asm("cvt.rna.tf32.f32 %0, %1;" : "=r"(u) : "f"(x)); return u;
}
__device__ __forceinline__ unsigned fu(float x) { return __float_as_uint(x); }

__device__ __forceinline__ void mma8(float* d,
                                     unsigned a0, unsigned a1, unsigned a2, unsigned a3,
                                     unsigned b0, unsigned b1) {
    asm volatile(
        "mma.sync.aligned.m16n8k8.row.col.f32.tf32.tf32.f32 "
        "{%0,%1,%2,%3},{%4,%5,%6,%7},{%8,%9},{%0,%1,%2,%3};\n"
        : "+f"(d[0]), "+f"(d[1]), "+f"(d[2]), "+f"(d[3])
        : "r"(a0), "r"(a1), "r"(a2), "r"(a3), "r"(b0), "r"(b1));
}

__device__ __forceinline__ void cp16_cg(unsigned d, const void* s) {
    asm volatile("cp.async.cg.shared.global [%0],[%1],16;\n" :: "r"(d), "l"(s));
}
__device__ __forceinline__ void cp16_ca(unsigned d, const void* s) {
    asm volatile("cp.async.ca.shared.global [%0],[%1],16;\n" :: "r"(d), "l"(s));
}
#define CP_COMMIT  asm volatile("cp.async.commit_group;\n")
#define CP_WAIT(n) asm volatile("cp.async.wait_group %0;\n" :: "n"(n))

__device__ __forceinline__ float sigm_f(float x) {
    return __fdividef(1.f, 1.f + __expf(-x));
}
__device__ __forceinline__ float tanh_f(float x) {
    float e = __expf(-2.f * fabsf(x));
    float r = __fdividef(1.f - e, 1.f + e);
    return copysignf(r, x);
}

// ---------------- init (must run every launch: graph replays reuse globals) ---
__global__ void init_k() {
    int i = blockIdx.x * 256 + threadIdx.x;
    if (i < 131072) g_h[i] = 0.f;
    if (i == 0) { g_count = 0; g_gen = 0; }
}

// ---------------- weight packers ----------------------------------------------
// Permuted column index p in [0,4096): p = cta*32 + l, l = gate*8 + ul,
// original n = gate*1024 + cta*8 + ul.
// WxP fragment pack over p-columns: n8-tile nt covers p in [nt*8, nt*8+8).
__global__ void pack_wx(const float* __restrict__ Wx) {
    int i = blockIdx.x * 256 + threadIdx.x;          // f2 index, 1,048,576 total
    int lane = i & 31, ks = (i >> 5) & 63, nt = i >> 11;
    int qn = lane >> 2, qk = lane & 3;
    int n = (nt & 3) * 1024 + (nt >> 2) * 8 + qn;    // gate = nt&3, ctaU = nt>>2
    int k = ks * 8 + qk;
    float2 v;
    v.x = __uint_as_float(f2tf32(Wx[(size_t)k * NG + n]));
    v.y = __uint_as_float(f2tf32(Wx[(size_t)(k + 4) * NG + n]));
    reinterpret_cast<float2*>(g_WxP)[i] = v;
}

__global__ void pack_wh(const float* __restrict__ Wh) {
    int i = blockIdx.x * 256 + threadIdx.x;          // f2 index, 2,097,152 total
    int lane = i & 31, ks = (i >> 5) & 127;
    int gate = (i >> 12) & 3, cta = i >> 14;
    int qn = lane >> 2, qk = lane & 3;
    int n = gate * 1024 + cta * 8 + qn;
    int k = ks * 8 + qk;
    float2 v;
    v.x = __uint_as_float(f2tf32(Wh[(size_t)k * NG + n]));
    v.y = __uint_as_float(f2tf32(Wh[(size_t)(k + 4) * NG + n]));
    reinterpret_cast<float2*>(g_WhP)[i] = v;
}

// ---------------- x-projection GEMM -------------------------------------------
// [65536 x 512] @ [512 x 4096(permuted)] + bias -> g_xproj permuted layout.
// CTA tile 128m x 64p, 256 threads (warp grid 4m x 2n), K-chunk 16, double buffer.
// grid (64 ptiles, 512 mtiles): consecutive CTAs share the X tile (L2), WxP (8MB) L2-resident.
__global__ void __launch_bounds__(256) xproj_gemm(const float* __restrict__ X,
                                                  const float* __restrict__ bias) {
    __shared__ float Xs[2][128 * 20];   // pad 20 -> conflict-free A frags
    __shared__ float Bs[2][1024];       // 512 f2: [nt(8)][ks(2)][lane(32)]

    int tid = threadIdx.x, lane = tid & 31, w = tid >> 5;
    int wm = w & 3, wn = w >> 2;
    int m0 = blockIdx.y * 128;
    int p0 = blockIdx.x * 64;
    int qm = lane >> 2, qk = lane & 3;

    unsigned xs_b = (unsigned)__cvta_generic_to_shared(&Xs[0][0]);
    unsigned bs_b = (unsigned)__cvta_generic_to_shared(&Bs[0][0]);

    float acc[2][4][4];
    #pragma unroll
    for (int mm = 0; mm < 2; mm++)
        #pragma unroll
        for (int j = 0; j < 4; j++)
            #pragma unroll
            for (int q = 0; q < 4; q++) acc[mm][j][q] = 0.f;

    auto stage = [&](int ch, int buf) {
        #pragma unroll
        for (int p = 0; p < 2; p++) {                       // X tile: 128r x 16k
            int idx = p * 256 + tid;
            int r = idx >> 2, c4 = (idx & 3) * 4;
            cp16_cg(xs_b + (unsigned)(buf * 2560 + r * 20 + c4) * 4,
                    X + (size_t)(m0 + r) * DD + ch * 16 + c4);
        }
        {                                                   // WxP fragments
            int nt = tid >> 5, q = tid & 31;
            const float* src = g_WxP +
                ((size_t)((p0 >> 3) + nt) * 64 + ch * 2) * 64 + q * 4;
            cp16_ca(bs_b + (unsigned)(buf * 1024 + nt * 128 + q * 4) * 4, src);
        }
    };

    stage(0, 0); CP_COMMIT;

    for (int ch = 0; ch < 32; ch++) {
        if (ch < 31) { stage(ch + 1, (ch + 1) & 1); CP_COMMIT; CP_WAIT(1); }
        else         { CP_WAIT(0); }
        __syncthreads();
        int buf = ch & 1;
        #pragma unroll
        for (int ksl = 0; ksl < 2; ksl++) {
            unsigned a[2][4];
            #pragma unroll
            for (int mm = 0; mm < 2; mm++) {
                const float* ap = &Xs[buf][(wm * 32 + mm * 16 + qm) * 20 + ksl * 8 + qk];
                a[mm][0] = fu(ap[0]);
                a[mm][1] = fu(ap[8 * 20]);
                a[mm][2] = fu(ap[4]);
                a[mm][3] = fu(ap[8 * 20 + 4]);
            }
            #pragma unroll
            for (int j = 0; j < 4; j++) {
                float2 bv = *reinterpret_cast<const float2*>(
                    &Bs[buf][((wn * 4 + j) * 2 + ksl) * 64 + lane * 2]);
                mma8(acc[0][j], a[0][0], a[0][1], a[0][2], a[0][3], fu(bv.x), fu(bv.y));
                mma8(acc[1][j], a[1][0], a[1][1], a[1][2], a[1][3], fu(bv.x), fu(bv.y));
            }
        }
        __syncthreads();
    }

    // epilogue: +bias (original column order), scatter to permuted layout
    #pragma unroll
    for (int j = 0; j < 4; j++) {
        int p = p0 + wn * 32 + j * 8 + qk * 2;              // even
        int gate = (p & 31) >> 3, ctaU = p >> 5, ul = p & 7;
        float2 bb = *reinterpret_cast<const float2*>(bias + gate * 1024 + ctaU * 8 + ul);
        #pragma unroll
        for (int mm = 0; mm < 2; mm++)
            #pragma unroll
            for (int r8 = 0; r8 < 2; r8++) {
                int m = m0 + wm * 32 + mm * 16 + qm + r8 * 8;
                int bi = m >> 10, t = m & 1023;
                float2 v;
                v.x = acc[mm][j][r8 * 2 + 0] + bb.x;
                v.y = acc[mm][j][r8 * 2 + 1] + bb.y;
                *reinterpret_cast<float2*>(
                    g_xproj + (((size_t)t * 128 + ctaU) * 64 + bi) * 32 + (p & 31)) = v;
            }
    }
}

// ---------------- grid barrier (128 co-resident CTAs, 1 CTA/SM) ---------------
__device__ __forceinline__ void gbar(unsigned target) {
    __threadfence();
    __syncthreads();
    if (threadIdx.x == 0) {
        unsigned old = atomicAdd(&g_count, 1);
        if (old == NCTA - 1) {
            g_count = 0;
            __threadfence();
            asm volatile("st.global.release.gpu.u32 [%0], %1;"
                         :: "l"(&g_gen), "r"(target) : "memory");
        } else {
            unsigned v;
            do {
                asm volatile("ld.global.acquire.gpu.u32 %0, [%1];"
                             : "=r"(v) : "l"(&g_gen) : "memory");
            } while (v < target);
        }
    }
    __syncthreads();
}

// ---------------- persistent recurrent kernel ---------------------------------
// CTA cta owns hidden units [cta*8, cta*8+8) -> 32 permuted gate columns.
// Per step: G[64x32] = h_prev[64x1024] @ WhP(cta) ; +xp ; activations ; c,h ; out.
__global__ void __launch_bounds__(256, 1) lstm_rec(float* __restrict__ out) {
    __shared__ float h_s[2][64 * 36];    // [buf][b][k32 + pad4]  (bank-safe A frags)
    __shared__ float Bs[2][1024];        // [buf][gate(4)][s(4)][lane(32)] f2
    __shared__ float gates_s[64 * 34];   // [b][l pad34]  (f2-aligned, 2-way max)
    __shared__ float xp_s[2048];         // [b][l(32)]
    __shared__ float hn_s[512];          // [ul][b]
    __shared__ float c_s[512];           // [ul][b]

    int tid = threadIdx.x, lane = tid & 31, w = tid >> 5;
    int mt = w & 3, nh = w >> 2;
    int m0 = mt * 16;
    int cta = blockIdx.x;
    int qm = lane >> 2, qk = lane & 3;

    unsigned hs_b = (unsigned)__cvta_generic_to_shared(&h_s[0][0]);
    unsigned bs_b = (unsigned)__cvta_generic_to_shared(&Bs[0][0]);
    unsigned xp_b = (unsigned)__cvta_generic_to_shared(&xp_s[0]);

    for (int i = tid; i < 512; i += 256) c_s[i] = 0.f;
    __syncthreads();

    const float* whbase = g_WhP + (size_t)cta * (4 * 128 * 32 * 2);
    float acc[2][4];
    #pragma unroll
    for (int j = 0; j < 2; j++)
        #pragma unroll
        for (int q = 0; q < 4; q++) acc[j][q] = 0.f;

    for (int t = 0; t < TT; t++) {
        int cur = t & 1, nxt = cur ^ 1;
        const float* hsrc = g_h + (size_t)cur * 65536;

        auto stage_chunk = [&](int ch, int buf) {
            #pragma unroll
            for (int p = 0; p < 2; p++) {              // A: 64 b-rows x 32 k
                int idx = p * 256 + tid;
                int b = idx >> 3, off = (idx & 7) * 4;
                cp16_cg(hs_b + (unsigned)(buf * 2304 + b * 36 + off) * 4,
                        hsrc + b * 1024 + ch * 32 + off);
            }
            {                                          // B: 4 gates x 4 ks x 32 f2
                int g = tid >> 6, q = tid & 63;
                const float* src = whbase + (((size_t)g * 128 + ch * 4) * 32 + q * 2) * 2;
                cp16_ca(bs_b + (unsigned)(buf * 1024 + g * 256 + q * 4) * 4, src);
            }
        };

        {   // stage xp slice (read once per step) + chunk 0
            const float* xsrc = g_xproj + ((size_t)t * 128 + cta) * 2048;
            #pragma unroll
            for (int p = 0; p < 2; p++) {
                int idx = p * 256 + tid;
                cp16_cg(xp_b + (unsigned)idx * 16, xsrc + idx * 4);
            }
            stage_chunk(0, 0);
            CP_COMMIT;
        }

        for (int ch = 0; ch < 32; ch++) {
            if (ch < 31) { stage_chunk(ch + 1, (ch + 1) & 1); CP_COMMIT; CP_WAIT(1); }
            else         { CP_WAIT(0); }
            __syncthreads();
            int buf = ch & 1;
            #pragma unroll
            for (int s = 0; s < 4; s++) {
                const float* ap = &h_s[buf][(m0 + qm) * 36 + s * 8 + qk];
                unsigned a0 = fu(ap[0]);
                unsigned a1 = fu(ap[8 * 36]);
                unsigned a2 = fu(ap[4]);
                unsigned a3 = fu(ap[8 * 36 + 4]);
                #pragma unroll
                for (int j = 0; j < 2; j++) {
                    float2 bv = *reinterpret_cast<const float2*>(
                        &Bs[buf][((nh * 2 + j) * 4 + s) * 64 + lane * 2]);
                    mma8(acc[j], a0, a1, a2, a3, fu(bv.x), fu(bv.y));
                }
            }
            __syncthreads();
        }

        // spill gate tiles to smem; reset accumulators
        #pragma unroll
        for (int j = 0; j < 2; j++) {
            int col = nh * 16 + j * 8 + qk * 2;
            *reinterpret_cast<float2*>(&gates_s[(m0 + qm) * 34 + col]) =
                make_float2(acc[j][0], acc[j][1]);
            *reinterpret_cast<float2*>(&gates_s[(m0 + qm + 8) * 34 + col]) =
                make_float2(acc[j][2], acc[j][3]);
            acc[j][0] = acc[j][1] = acc[j][2] = acc[j][3] = 0.f;
        }
        __syncthreads();

        // cell update: thread handles (b = tid&63, ul = tid>>6 and +4)
        {
            int b = tid & 63, ub = tid >> 6;
            #pragma unroll
            for (int hh = 0; hh < 2; hh++) {
                int ul = ub + hh * 4;
                float xi = gates_s[b * 34 + ul]      + xp_s[b * 32 + ul];
                float xf = gates_s[b * 34 + 8 + ul]  + xp_s[b * 32 + 8 + ul];
                float xg = gates_s[b * 34 + 16 + ul] + xp_s[b * 32 + 16 + ul];
                float xo = gates_s[b * 34 + 24 + ul] + xp_s[b * 32 + 24 + ul];
                float ig = sigm_f(xi), fg = sigm_f(xf);
                float gg = tanh_f(xg), og = sigm_f(xo);
                float cc = fg * c_s[ul * 64 + b] + ig * gg;
                c_s[ul * 64 + b] = cc;
                hn_s[ul * 64 + b] = og * tanh_f(cc);
            }
        }
        __syncthreads();

        // coalesced h-state + output writes (threads 0..63, one per batch)
        if (tid < 64) {
            float4 v0 = make_float4(hn_s[0 * 64 + tid], hn_s[1 * 64 + tid],
                                    hn_s[2 * 64 + tid], hn_s[3 * 64 + tid]);
            float4 v1 = make_float4(hn_s[4 * 64 + tid], hn_s[5 * 64 + tid],
                                    hn_s[6 * 64 + tid], hn_s[7 * 64 + tid]);
            float* hd = g_h + (size_t)nxt * 65536 + tid * 1024 + cta * 8;
            *reinterpret_cast<float4*>(hd) = v0;
            *reinterpret_cast<float4*>(hd + 4) = v1;
            float* od = out + ((size_t)tid * 1024 + t) * 1024 + cta * 8;
            *reinterpret_cast<float4*>(od) = v0;
            *reinterpret_cast<float4*>(od + 4) = v1;
        }

        gbar((unsigned)(t + 1));
    }
}

// ---------------- entry --------------------------------------------------------
extern "C" void kernel_launch(void* const* d_in, const int* in_sizes, int n_in,
                              void* d_out, int out_size) {
    const float* X  = (const float*)d_in[0];   // [64,1024,512]
    const float* Wx = (const float*)d_in[1];   // [512,4096]
    const float* Wh = (const float*)d_in[2];   // [1024,4096]
    const float* bv = (const float*)d_in[3];   // [4096]
    float* out = (float*)d_out;                // [64,1024,1024]

    init_k<<<512, 256>>>();
    pack_wx<<<4096, 256>>>(Wx);
    pack_wh<<<8192, 256>>>(Wh);
    xproj_gemm<<<dim3(64, 512), 256>>>(X, bv);
    lstm_rec<<<NCTA, 256>>>(out);
}

// round 3
// speedup vs baseline: 1.1423x; 1.1423x over previous
#include <cuda_runtime.h>
#include <cstdint>
#include <cstddef>

// Problem constants
#define BB   64
#define TT   1024
#define DD   512
#define HH   1024
#define NG   4096
#define NCTA 128

// ---------------- device scratch (allocation-free, __device__ globals) --------
__device__ float g_xproj[268435456];   // 1 GiB: [t][cta(128)][b(64)][l(32)]
__device__ float g_WhP[4194304];       // 16 MB: f2[((cta*4+gate)*128+ks)*32+lane]
__device__ float g_WxP[2097152];       //  8 MB: f2[(nt*64+ks)*32+lane]
__device__ float g_h[131072];          // [2][b(64)][k(1024)]
__device__ unsigned g_count;
__device__ unsigned g_gen;

// ---------------- helpers -----------------------------------------------------
__device__ __forceinline__ unsigned f2tf32(float x) {
    unsigned u; asm("cvt.rna.tf32.f32 %0, %1;" : "=r"(u) : "f"(x)); return u;
}
__device__ __forceinline__ unsigned fu(float x) { return __float_as_uint(x); }

__device__ __forceinline__ void mma8(float* d,
                                     unsigned a0, unsigned a1, unsigned a2, unsigned a3,
                                     unsigned b0, unsigned b1) {
    asm volatile(
        "mma.sync.aligned.m16n8k8.row.col.f32.tf32.tf32.f32 "
        "{%0,%1,%2,%3},{%4,%5,%6,%7},{%8,%9},{%0,%1,%2,%3};\n"
        : "+f"(d[0]), "+f"(d[1]), "+f"(d[2]), "+f"(d[3])
        : "r"(a0), "r"(a1), "r"(a2), "r"(a3), "r"(b0), "r"(b1));
}

__device__ __forceinline__ void cp16_cg(unsigned d, const void* s) {
    asm volatile("cp.async.cg.shared.global [%0],[%1],16;\n" :: "r"(d), "l"(s));
}
__device__ __forceinline__ void cp16_ca(unsigned d, const void* s) {
    asm volatile("cp.async.ca.shared.global [%0],[%1],16;\n" :: "r"(d), "l"(s));
}
#define CP_COMMIT  asm volatile("cp.async.commit_group;\n")
#define CP_WAIT(n) asm volatile("cp.async.wait_group %0;\n" :: "n"(n))

__device__ __forceinline__ float sigm_f(float x) {
    return __fdividef(1.f, 1.f + __expf(-x));
}
__device__ __forceinline__ float tanh_f(float x) {
    float e = __expf(-2.f * fabsf(x));
    float r = __fdividef(1.f - e, 1.f + e);
    return copysignf(r, x);
}

// ---------------- init (must run every launch: graph replays reuse globals) ---
__global__ void init_k() {
    int i = blockIdx.x * 256 + threadIdx.x;
    if (i < 131072) g_h[i] = 0.f;
    if (i == 0) { g_count = 0; g_gen = 0; }
}

// ---------------- weight packers ----------------------------------------------
// Permuted column index p in [0,4096): p = cta*32 + l, l = gate*8 + ul,
// original n = gate*1024 + cta*8 + ul.
__global__ void pack_wx(const float* __restrict__ Wx) {
    int i = blockIdx.x * 256 + threadIdx.x;          // f2 index, 1,048,576 total
    int lane = i & 31, ks = (i >> 5) & 63, nt = i >> 11;
    int qn = lane >> 2, qk = lane & 3;
    int n = (nt & 3) * 1024 + (nt >> 2) * 8 + qn;    // gate = nt&3, ctaU = nt>>2
    int k = ks * 8 + qk;
    float2 v;
    v.x = __uint_as_float(f2tf32(Wx[(size_t)k * NG + n]));
    v.y = __uint_as_float(f2tf32(Wx[(size_t)(k + 4) * NG + n]));
    reinterpret_cast<float2*>(g_WxP)[i] = v;
}

__global__ void pack_wh(const float* __restrict__ Wh) {
    int i = blockIdx.x * 256 + threadIdx.x;          // f2 index, 2,097,152 total
    int lane = i & 31, ks = (i >> 5) & 127;
    int gate = (i >> 12) & 3, cta = i >> 14;
    int qn = lane >> 2, qk = lane & 3;
    int n = gate * 1024 + cta * 8 + qn;
    int k = ks * 8 + qk;
    float2 v;
    v.x = __uint_as_float(f2tf32(Wh[(size_t)k * NG + n]));
    v.y = __uint_as_float(f2tf32(Wh[(size_t)(k + 4) * NG + n]));
    reinterpret_cast<float2*>(g_WhP)[i] = v;
}

// ---------------- x-projection GEMM -------------------------------------------
// [65536 x 512] @ [512 x 4096(permuted)] + bias -> g_xproj permuted layout.
// CTA tile 128m x 64p, 256 threads (warp grid 4m x 2n), K-chunk 16, double buffer.
// Epilogue staged through smem -> 128B coalesced row stores.
// Dynamic smem: staging 7168 floats (Xs 5120 + Bs 2048), reused as out 128x66.
__global__ void __launch_bounds__(256) xproj_gemm(const float* __restrict__ X,
                                                  const float* __restrict__ bias) {
    extern __shared__ float sm[];
    float* Xs = sm;             // [2][128*20]
    float* Bsm = sm + 5120;     // [2][1024]

    int tid = threadIdx.x, lane = tid & 31, w = tid >> 5;
    int wm = w & 3, wn = w >> 2;
    int m0 = blockIdx.y * 128;
    int p0 = blockIdx.x * 64;
    int qm = lane >> 2, qk = lane & 3;

    unsigned xs_b = (unsigned)__cvta_generic_to_shared(Xs);
    unsigned bs_b = (unsigned)__cvta_generic_to_shared(Bsm);

    float acc[2][4][4];
    #pragma unroll
    for (int mm = 0; mm < 2; mm++)
        #pragma unroll
        for (int j = 0; j < 4; j++)
            #pragma unroll
            for (int q = 0; q < 4; q++) acc[mm][j][q] = 0.f;

    auto stage = [&](int ch, int buf) {
        #pragma unroll
        for (int p = 0; p < 2; p++) {                       // X tile: 128r x 16k
            int idx = p * 256 + tid;
            int r = idx >> 2, c4 = (idx & 3) * 4;
            cp16_cg(xs_b + (unsigned)(buf * 2560 + r * 20 + c4) * 4,
                    X + (size_t)(m0 + r) * DD + ch * 16 + c4);
        }
        {                                                   // WxP fragments
            int nt = tid >> 5, q = tid & 31;
            const float* src = g_WxP +
                ((size_t)((p0 >> 3) + nt) * 64 + ch * 2) * 64 + q * 4;
            cp16_ca(bs_b + (unsigned)(buf * 1024 + nt * 128 + q * 4) * 4, src);
        }
    };

    stage(0, 0); CP_COMMIT;

    for (int ch = 0; ch < 32; ch++) {
        if (ch < 31) { stage(ch + 1, (ch + 1) & 1); CP_COMMIT; CP_WAIT(1); }
        else         { CP_WAIT(0); }
        __syncthreads();
        int buf = ch & 1;
        #pragma unroll
        for (int ksl = 0; ksl < 2; ksl++) {
            unsigned a[2][4];
            #pragma unroll
            for (int mm = 0; mm < 2; mm++) {
                const float* ap = &Xs[buf * 2560 + (wm * 32 + mm * 16 + qm) * 20 + ksl * 8 + qk];
                a[mm][0] = fu(ap[0]);
                a[mm][1] = fu(ap[8 * 20]);
                a[mm][2] = fu(ap[4]);
                a[mm][3] = fu(ap[8 * 20 + 4]);
            }
            #pragma unroll
            for (int j = 0; j < 4; j++) {
                float2 bv = *reinterpret_cast<const float2*>(
                    &Bsm[buf * 1024 + ((wn * 4 + j) * 2 + ksl) * 64 + lane * 2]);
                mma8(acc[0][j], a[0][0], a[0][1], a[0][2], a[0][3], fu(bv.x), fu(bv.y));
                mma8(acc[1][j], a[1][0], a[1][1], a[1][2], a[1][3], fu(bv.x), fu(bv.y));
            }
        }
        __syncthreads();
    }

    // ---- epilogue v2: +bias, stage tile in smem, coalesced 128B row stores ----
    float* outs = sm;   // reuse staging region: [128][66]
    #pragma unroll
    for (int j = 0; j < 4; j++) {
        int colp = wn * 32 + j * 8 + qk * 2;
        int p = p0 + colp;
        int gate = (p & 31) >> 3, ctaU = p >> 5, ul = p & 7;
        float2 bb = *reinterpret_cast<const float2*>(bias + gate * 1024 + ctaU * 8 + ul);
        #pragma unroll
        for (int mm = 0; mm < 2; mm++) {
            int ml = wm * 32 + mm * 16 + qm;
            *reinterpret_cast<float2*>(&outs[ml * 66 + colp]) =
                make_float2(acc[mm][j][0] + bb.x, acc[mm][j][1] + bb.y);
            *reinterpret_cast<float2*>(&outs[(ml + 8) * 66 + colp]) =
                make_float2(acc[mm][j][2] + bb.x, acc[mm][j][3] + bb.y);
        }
    }
    __syncthreads();
    #pragma unroll
    for (int it = 0; it < 32; it++) {
        int rc = it * 8 + w;
        int ml = rc >> 1, u2 = rc & 1;
        int m = m0 + ml;
        int t = m & 1023, bi = m >> 10;
        float v = outs[ml * 66 + u2 * 32 + lane];
        g_xproj[(((size_t)t * 128 + (p0 >> 5) + u2) * 64 + bi) * 32 + lane] = v;
    }
}

// ---------------- grid barrier (128 co-resident CTAs, 1 CTA/SM) ---------------
__device__ __forceinline__ void gbar(unsigned target) {
    __threadfence();
    __syncthreads();
    if (threadIdx.x == 0) {
        unsigned old = atomicAdd(&g_count, 1);
        if (old == NCTA - 1) {
            g_count = 0;
            __threadfence();
            asm volatile("st.global.release.gpu.u32 [%0], %1;"
                         :: "l"(&g_gen), "r"(target) : "memory");
        } else {
            unsigned v;
            do {
                asm volatile("ld.global.acquire.gpu.u32 %0, [%1];"
                             : "=r"(v) : "l"(&g_gen) : "memory");
            } while (v < target);
        }
    }
    __syncthreads();
}

// ---------------- persistent recurrent kernel v2 ------------------------------
// CTA cta owns hidden units [cta*8, cta*8+8) -> 32 permuted gate columns.
// Warp w owns interleaved k8 tiles {w + 8*si}, si=0..15. Wh B-fragments live in
// registers (128/thread). Each warp stages its own h columns (no K-loop syncs),
// then one smem reduction across warps per step.
// Dynamic smem (floats): ws[8][2][64][20] @0 (20480), red[8][64][34] @20480
// (17408), xp[64][32] @37888 (2048), c[8][64] @39936, hn[8][64] @40448.
__global__ void __launch_bounds__(256, 1) lstm_rec(float* __restrict__ out) {
    extern __shared__ float sm[];
    float* ws  = sm;
    float* red = sm + 20480;
    float* xp  = sm + 37888;
    float* cs  = sm + 39936;
    float* hns = sm + 40448;

    int tid = threadIdx.x, lane = tid & 31, w = tid >> 5;
    int cta = blockIdx.x;
    int qm = lane >> 2, qk = lane & 3;

    unsigned ws_b = (unsigned)__cvta_generic_to_shared(ws);
    unsigned xp_b = (unsigned)__cvta_generic_to_shared(xp);

    // ---- load Wh B-fragments into registers (once) ----
    float2 bf[4][16];
    {
        const float2* whp = reinterpret_cast<const float2*>(g_WhP)
                            + ((size_t)cta * 4 * 128) * 32;
        #pragma unroll
        for (int g = 0; g < 4; g++)
            #pragma unroll
            for (int si = 0; si < 16; si++)
                bf[g][si] = __ldg(&whp[((size_t)g * 128 + (w + 8 * si)) * 32 + lane]);
    }

    for (int i = tid; i < 512; i += 256) cs[i] = 0.f;
    __syncthreads();

    float acc[4][4][4];
    #pragma unroll
    for (int mt = 0; mt < 4; mt++)
        #pragma unroll
        for (int j = 0; j < 4; j++)
            #pragma unroll
            for (int q = 0; q < 4; q++) acc[mt][j][q] = 0.f;

    for (int t = 0; t < TT; t++) {
        int cur = t & 1, nxt = cur ^ 1;
        const float* hsrc = g_h + (size_t)cur * 65536;

        // per-warp staging of own h columns: chunk ch covers k [ch*128,(ch+1)*128)
        auto stage = [&](int ch, int buf) {
            const float* src0 = hsrc + ch * 128 + w * 8;
            unsigned dst0 = ws_b + (unsigned)((w * 2 + buf) * 1280) * 4;
            #pragma unroll
            for (int it = 0; it < 8; it++) {
                int idx = it * 32 + lane;
                int r = idx >> 2, g = (idx >> 1) & 1, hf = idx & 1;
                cp16_cg(dst0 + (unsigned)(r * 20 + g * 8 + hf * 4) * 4,
                        src0 + r * 1024 + g * 64 + hf * 4);
            }
        };

        // prologue: xp slice + chunk 0 in one group
        {
            const float* xsrc = g_xproj + ((size_t)t * 128 + cta) * 2048;
            #pragma unroll
            for (int p = 0; p < 2; p++) {
                int idx = p * 256 + tid;
                cp16_cg(xp_b + (unsigned)idx * 16, xsrc + idx * 4);
            }
            stage(0, 0);
            CP_COMMIT;
        }

        #pragma unroll
        for (int ch = 0; ch < 8; ch++) {
            if (ch < 7) { stage(ch + 1, (ch + 1) & 1); CP_COMMIT; CP_WAIT(1); }
            else        { CP_WAIT(0); }
            const float* wsb = ws + (w * 2 + (ch & 1)) * 1280;
            #pragma unroll
            for (int g = 0; g < 2; g++) {
                #pragma unroll
                for (int mt = 0; mt < 4; mt++) {
                    const float* ap = wsb + (mt * 16 + qm) * 20 + g * 8 + qk;
                    unsigned a0 = fu(ap[0]);
                    unsigned a1 = fu(ap[8 * 20]);
                    unsigned a2 = fu(ap[4]);
                    unsigned a3 = fu(ap[8 * 20 + 4]);
                    #pragma unroll
                    for (int j = 0; j < 4; j++)
                        mma8(acc[mt][j], a0, a1, a2, a3,
                             fu(bf[j][2 * ch + g].x), fu(bf[j][2 * ch + g].y));
                }
            }
        }

        // ---- spill per-warp partials to reduction slabs ----
        {
            float* myred = red + w * (64 * 34);
            #pragma unroll
            for (int mt = 0; mt < 4; mt++)
                #pragma unroll
                for (int j = 0; j < 4; j++) {
                    int b0 = mt * 16 + qm, col = j * 8 + qk * 2;
                    *reinterpret_cast<float2*>(&myred[b0 * 34 + col]) =
                        make_float2(acc[mt][j][0], acc[mt][j][1]);
                    *reinterpret_cast<float2*>(&myred[(b0 + 8) * 34 + col]) =
                        make_float2(acc[mt][j][2], acc[mt][j][3]);
                    acc[mt][j][0] = 0.f; acc[mt][j][1] = 0.f;
                    acc[mt][j][2] = 0.f; acc[mt][j][3] = 0.f;
                }
        }
        __syncthreads();

        // ---- reduce across 8 warps + cell update ----
        {
            int b = tid & 63, u2 = tid >> 6;
            float gs[4][2];
            #pragma unroll
            for (int g = 0; g < 4; g++) { gs[g][0] = 0.f; gs[g][1] = 0.f; }
            #pragma unroll
            for (int wi = 0; wi < 8; wi++) {
                const float* rp = red + (wi * 64 + b) * 34;
                #pragma unroll
                for (int g = 0; g < 4; g++) {
                    float2 v = *reinterpret_cast<const float2*>(&rp[g * 8 + u2 * 2]);
                    gs[g][0] += v.x; gs[g][1] += v.y;
                }
            }
            #pragma unroll
            for (int hh = 0; hh < 2; hh++) {
                int ul = u2 * 2 + hh;
                float xi = gs[0][hh] + xp[b * 32 + ul];
                float xf = gs[1][hh] + xp[b * 32 + 8 + ul];
                float xg = gs[2][hh] + xp[b * 32 + 16 + ul];
                float xo = gs[3][hh] + xp[b * 32 + 24 + ul];
                float ig = sigm_f(xi), fg = sigm_f(xf);
                float gg = tanh_f(xg), og = sigm_f(xo);
                float cc = fg * cs[ul * 64 + b] + ig * gg;
                cs[ul * 64 + b] = cc;
                hns[ul * 64 + b] = og * tanh_f(cc);
            }
        }
        __syncthreads();

        // ---- coalesced h-state + output writes (one thread per batch row) ----
        if (tid < 64) {
            float4 v0 = make_float4(hns[0 * 64 + tid], hns[1 * 64 + tid],
                                    hns[2 * 64 + tid], hns[3 * 64 + tid]);
            float4 v1 = make_float4(hns[4 * 64 + tid], hns[5 * 64 + tid],
                                    hns[6 * 64 + tid], hns[7 * 64 + tid]);
            float* hd = g_h + (size_t)nxt * 65536 + tid * 1024 + cta * 8;
            *reinterpret_cast<float4*>(hd) = v0;
            *reinterpret_cast<float4*>(hd + 4) = v1;
            float* od = out + ((size_t)tid * 1024 + t) * 1024 + cta * 8;
            *reinterpret_cast<float4*>(od) = v0;
            *reinterpret_cast<float4*>(od + 4) = v1;
        }

        gbar((unsigned)(t + 1));
    }
}

// ---------------- entry --------------------------------------------------------
extern "C" void kernel_launch(void* const* d_in, const int* in_sizes, int n_in,
                              void* d_out, int out_size) {
    const float* X  = (const float*)d_in[0];   // [64,1024,512]
    const float* Wx = (const float*)d_in[1];   // [512,4096]
    const float* Wh = (const float*)d_in[2];   // [1024,4096]
    const float* bv = (const float*)d_in[3];   // [4096]
    float* out = (float*)d_out;                // [64,1024,1024]

    cudaFuncSetAttribute(xproj_gemm, cudaFuncAttributeMaxDynamicSharedMemorySize, 33792);
    cudaFuncSetAttribute(lstm_rec,   cudaFuncAttributeMaxDynamicSharedMemorySize, 163840);

    init_k<<<512, 256>>>();
    pack_wx<<<4096, 256>>>(Wx);
    pack_wh<<<8192, 256>>>(Wh);
    xproj_gemm<<<dim3(64, 512), 256, 33792>>>(X, bv);
    lstm_rec<<<NCTA, 256, 163840>>>(out);
}